// round 3
// baseline (speedup 1.0000x reference)
#include <cuda_runtime.h>
#include <cstdint>

typedef unsigned int       u32;
typedef unsigned long long u64;

static __device__ __forceinline__ u64 ffma2(u64 a, u64 b, u64 c){
    u64 d; asm("fma.rn.f32x2 %0, %1, %2, %3;" : "=l"(d) : "l"(a), "l"(b), "l"(c)); return d;
}
static __device__ __forceinline__ u64 fadd2(u64 a, u64 b){
    u64 d; asm("add.rn.f32x2 %0, %1, %2;" : "=l"(d) : "l"(a), "l"(b)); return d;
}
static __device__ __forceinline__ u64 pack2(float x){
    u64 r; asm("mov.b64 %0, {%1, %1};" : "=l"(r) : "f"(x)); return r;
}
static __device__ __forceinline__ float2 unpack2(u64 v){
    float lo, hi; asm("mov.b64 {%0, %1}, %2;" : "=f"(lo), "=f"(hi) : "l"(v)); return make_float2(lo, hi);
}

// ---------------- smem layout (float offsets) ----------------
#define SW1   0        // W1 compact [36][64]            = 2304
#define SW2   2304     // W2 [64][64]                    = 4096
#define SB1   6400     // 64
#define SB2   6464     // 64
#define SWD   6528     // 64 u64 (W3 folded col-diffs)   = 128 floats
#define SCC   6656     // folded b3 diffs (u64)          = 2
#define SOBS  6660     // obs transposed [36][128]       = 4608
#define SH1   11268    // h1/g transposed [64][128] = 8192 ; overlapped with XST
#define XST   11268    // x staging: 64 rows * 141 (padded) = 9024
#define SMEM_FLOATS (11268 + 9024)          // 20292 floats = 81168 bytes

#define BPB   256      // threads per block
#define TILEB 128      // batches per block

__global__ __launch_bounds__(BPB, 2) void maddpg_gemm_kernel(
    const float* __restrict__ x,
    const float* __restrict__ W1, const float* __restrict__ b1,
    const float* __restrict__ W2, const float* __restrict__ b2,
    const float* __restrict__ W3, const float* __restrict__ b3,
    const int* __restrict__ idx,
    float* __restrict__ out, int B)
{
    extern __shared__ float sm[];
    __shared__ int sIdx[8];
    const int tid = threadIdx.x;
    const int tx  = tid & 31;    // batch group: batches 4*tx .. 4*tx+3
    const int ty  = tid >> 5;    // output group: outputs 8*ty .. 8*ty+7 (one warp = one ty)
    const int b0  = blockIdx.x * TILEB;

    // ---- weights into smem ----
    // W1 compacted to 36 rows (drop structurally-zero obs rows 7,10,13 of the original 39)
    #pragma unroll
    for (int i = tid; i < 36*64; i += BPB){
        int ck = i >> 6, n = i & 63;
        int o;
        if (ck < 5)       o = ck;
        else if (ck < 11) { int m = (ck-5) >> 1; o = 5 + 3*m + ((ck-5)&1); }
        else              o = 14 + (ck - 11);
        sm[SW1 + i] = W1[o*64 + n];
    }
    #pragma unroll
    for (int i = tid; i < 4096; i += BPB) sm[SW2 + i] = W2[i];
    if (tid < 64){
        sm[SB1 + tid] = b1[tid];
        sm[SB2 + tid] = b2[tid];
        float a1 = W3[tid*5+1], a2 = W3[tid*5+2], a3 = W3[tid*5+3], a4 = W3[tid*5+4];
        ((float2*)(sm + SWD))[tid] = make_float2(a1 - a2, a3 - a4);
    }
    if (tid == 0) *(float2*)(sm + SCC) = make_float2(b3[1]-b3[2], b3[3]-b3[4]);
    if (tid < 8) sIdx[tid] = idx[tid];

    // ---- stage x (2 chunks of 64 batches) and build transposed obs [36][128] ----
    const long gtot = (long)B * 140;
    #pragma unroll
    for (int c = 0; c < 2; c++){
        long gbase = (long)(b0 + 64*c) * 140;
        // scalar coalesced copy into rows padded to 141 floats (conflict-free reads later)
        for (int i = tid; i < 64*140; i += BPB){
            long gi = gbase + i;
            float v = (gi < gtot) ? x[gi] : 0.0f;
            sm[XST + (i/140)*141 + (i%140)] = v;
        }
        __syncthreads();
        if (tid < 64){
            const float* xb = sm + XST + tid*141;
            float* ob = sm + SOBS + (c*64 + tid);   // column for this batch
            const float p0 = xb[0], p1 = xb[1];
            ob[0*128] = p0;  ob[1*128] = p1;  ob[2*128] = xb[2];
            ob[3*128] = xb[3]; ob[4*128] = xb[4];
            #pragma unroll
            for (int m = 0; m < 3; m++){
                const float* r = xb + sIdx[m]*7;
                ob[(5+2*m)*128] = (r[5] + r[0]) - p0;
                ob[(6+2*m)*128] = (r[6] + r[1]) - p1;
            }
            #pragma unroll
            for (int m = 0; m < 5; m++){
                const float* r = xb + (sIdx[3+m] + 10)*7;
                float dx = r[0]-p0, dy = r[1]-p1;
                bool in = (dx*dx + dy*dy) < 0.0225f;   // RADIUS^2
                ob[(11+5*m+0)*128] = in ? dx   : 0.0f;
                ob[(11+5*m+1)*128] = in ? dy   : 0.0f;
                ob[(11+5*m+2)*128] = in ? r[2] : 0.0f;
                ob[(11+5*m+3)*128] = in ? r[3] : 0.0f;
                ob[(11+5*m+4)*128] = in ? r[4] : 0.0f;
            }
        }
        __syncthreads();
    }

    // ---- GEMM1: [128b x 36] * [36 x 64] ; micro-tile 4 batches x 8 outputs ----
    u64 acc[16];   // acc[b*4+p] = outputs (8ty+2p, 8ty+2p+1) for batch 4tx+b
    #pragma unroll
    for (int i = 0; i < 16; i++) acc[i] = 0ull;

    {
        const float* obs = sm + SOBS + 4*tx;
        const float* w   = sm + SW1  + 8*ty;
        #pragma unroll 6
        for (int k = 0; k < 36; k++){
            float4 a = *(const float4*)(obs + k*128);
            ulonglong2 w01 = *(const ulonglong2*)(w + k*64);
            ulonglong2 w23 = *(const ulonglong2*)(w + k*64 + 4);
            u64 wp[4] = { w01.x, w01.y, w23.x, w23.y };
            float av[4] = { a.x, a.y, a.z, a.w };
            #pragma unroll
            for (int b = 0; b < 4; b++){
                u64 ab = pack2(av[b]);
                #pragma unroll
                for (int p = 0; p < 4; p++)
                    acc[b*4+p] = ffma2(ab, wp[p], acc[b*4+p]);
            }
        }
    }

    // ---- epilogue 1: relu(acc + b1) -> SH1 [o][batch], float4 along batch ----
    {
        #pragma unroll
        for (int p = 0; p < 4; p++){
            float blo = sm[SB1 + 8*ty + 2*p];
            float bhi = sm[SB1 + 8*ty + 2*p + 1];
            float4 lo, hi;
            float2 f0 = unpack2(acc[0*4+p]);
            float2 f1 = unpack2(acc[1*4+p]);
            float2 f2 = unpack2(acc[2*4+p]);
            float2 f3 = unpack2(acc[3*4+p]);
            lo.x = fmaxf(f0.x + blo, 0.0f); lo.y = fmaxf(f1.x + blo, 0.0f);
            lo.z = fmaxf(f2.x + blo, 0.0f); lo.w = fmaxf(f3.x + blo, 0.0f);
            hi.x = fmaxf(f0.y + bhi, 0.0f); hi.y = fmaxf(f1.y + bhi, 0.0f);
            hi.z = fmaxf(f2.y + bhi, 0.0f); hi.w = fmaxf(f3.y + bhi, 0.0f);
            *(float4*)(sm + SH1 + (8*ty + 2*p    )*128 + 4*tx) = lo;
            *(float4*)(sm + SH1 + (8*ty + 2*p + 1)*128 + 4*tx) = hi;
        }
    }
    __syncthreads();

    // ---- GEMM2: [128b x 64] * [64 x 64] ----
    #pragma unroll
    for (int i = 0; i < 16; i++) acc[i] = 0ull;
    {
        const float* h = sm + SH1 + 4*tx;
        const float* w = sm + SW2 + 8*ty;
        #pragma unroll 8
        for (int k = 0; k < 64; k++){
            float4 a = *(const float4*)(h + k*128);
            ulonglong2 w01 = *(const ulonglong2*)(w + k*64);
            ulonglong2 w23 = *(const ulonglong2*)(w + k*64 + 4);
            u64 wp[4] = { w01.x, w01.y, w23.x, w23.y };
            float av[4] = { a.x, a.y, a.z, a.w };
            #pragma unroll
            for (int b = 0; b < 4; b++){
                u64 ab = pack2(av[b]);
                #pragma unroll
                for (int p = 0; p < 4; p++)
                    acc[b*4+p] = ffma2(ab, wp[p], acc[b*4+p]);
            }
        }
    }
    __syncthreads();   // all GEMM2 reads of SH1 done before g overwrites it

    // ---- epilogue 2: relu(acc + b2) -> SH1 (as g) ----
    {
        #pragma unroll
        for (int p = 0; p < 4; p++){
            float blo = sm[SB2 + 8*ty + 2*p];
            float bhi = sm[SB2 + 8*ty + 2*p + 1];
            float4 lo, hi;
            float2 f0 = unpack2(acc[0*4+p]);
            float2 f1 = unpack2(acc[1*4+p]);
            float2 f2 = unpack2(acc[2*4+p]);
            float2 f3 = unpack2(acc[3*4+p]);
            lo.x = fmaxf(f0.x + blo, 0.0f); lo.y = fmaxf(f1.x + blo, 0.0f);
            lo.z = fmaxf(f2.x + blo, 0.0f); lo.w = fmaxf(f3.x + blo, 0.0f);
            hi.x = fmaxf(f0.y + bhi, 0.0f); hi.y = fmaxf(f1.y + bhi, 0.0f);
            hi.z = fmaxf(f2.y + bhi, 0.0f); hi.w = fmaxf(f3.y + bhi, 0.0f);
            *(float4*)(sm + SH1 + (8*ty + 2*p    )*128 + 4*tx) = lo;
            *(float4*)(sm + SH1 + (8*ty + 2*p + 1)*128 + 4*tx) = hi;
        }
    }
    __syncthreads();

    // ---- fold with W3 diffs, scale, clip, store ----
    if (tid < TILEB){
        u64 a2 = *(const u64*)(sm + SCC);
        const u64* wd = (const u64*)(sm + SWD);
        const float* g = sm + SH1 + tid;
        #pragma unroll 8
        for (int o = 0; o < 64; o++)
            a2 = ffma2(pack2(g[o*128]), wd[o], a2);
        float2 r = unpack2(a2);
        float v0 = r.x * 0.1f, v1 = r.y * 0.1f;
        if (fabsf(v0) > 1.0f) v0 = copysignf(2.0f, v0);
        if (fabsf(v1) > 1.0f) v1 = copysignf(2.0f, v1);
        int b = b0 + tid;
        if (b < B) ((float2*)out)[b] = make_float2(v0, v1);
    }
}

extern "C" void kernel_launch(void* const* d_in, const int* in_sizes, int n_in,
                              void* d_out, int out_size)
{
    const float* x  = (const float*)d_in[0];
    const float* W1 = (const float*)d_in[1];
    const float* b1 = (const float*)d_in[2];
    const float* W2 = (const float*)d_in[3];
    const float* b2 = (const float*)d_in[4];
    const float* W3 = (const float*)d_in[5];
    const float* b3 = (const float*)d_in[6];
    const int*  idx = (const int*)d_in[7];

    const int B = in_sizes[0] / 140;
    const int blocks = (B + TILEB - 1) / TILEB;
    const size_t smem = SMEM_FLOATS * sizeof(float);

    cudaFuncSetAttribute(maddpg_gemm_kernel,
                         cudaFuncAttributeMaxDynamicSharedMemorySize, (int)smem);

    maddpg_gemm_kernel<<<blocks, BPB, smem>>>(x, W1, b1, W2, b2, W3, b3, idx,
                                              (float*)d_out, B);
}

// round 5
// speedup vs baseline: 1.4943x; 1.4943x over previous
#include <cuda_runtime.h>

typedef unsigned int       u32;
typedef unsigned long long u64;

static __device__ __forceinline__ u64 ffma2(u64 a, u64 b, u64 c){
    u64 d; asm("fma.rn.f32x2 %0, %1, %2, %3;" : "=l"(d) : "l"(a), "l"(b), "l"(c)); return d;
}
static __device__ __forceinline__ u64 pack2(float x){
    u64 r; asm("mov.b64 %0, {%1, %1};" : "=l"(r) : "f"(x)); return r;
}
static __device__ __forceinline__ float2 unpack2(u64 v){
    float lo, hi; asm("mov.b64 {%0, %1}, %2;" : "=f"(lo), "=f"(hi) : "l"(v)); return make_float2(lo, hi);
}
static __device__ __forceinline__ u32 smaddr(const void* p){
    u32 a; asm("{ .reg .u64 t; cvta.to.shared.u64 t, %1; cvt.u32.u64 %0, t; }" : "=r"(a) : "l"(p)); return a;
}
static __device__ __forceinline__ void cp8(u32 dst, const void* src){
    asm volatile("cp.async.ca.shared.global [%0], [%1], 8;" :: "r"(dst), "l"(src));
}
#define CP_COMMIT() asm volatile("cp.async.commit_group;" ::: "memory")
#define CP_WAIT0()  asm volatile("cp.async.wait_group 0;" ::: "memory")

// ---------------- smem layout (float offsets) ----------------
#define SW1   0        // W1 compact [36][64]                  = 2304
#define SW2   2304     // W2 [64][64]                          = 4096
#define SB1   6400     // 64
#define SB2   6464     // 64
#define SWD   6528     // 64 u64 (W3 folded col diffs)         = 128
#define SCC   6656     // folded b3 diffs                      = 2 (+2 pad)
#define SHR   6660     // SOBS [36][64] (2304) then SH1 [64][64] (4096) -> 4096
#define XST   10756    // 16 batches * 142 floats              = 2272
#define SMEM_FLOATS 13028          // 52112 bytes -> 4 CTAs/SM

#define BPB   128
#define TILEB 64

// one k-step of the register GEMM: 4 batches x 8 outputs per thread
#define K_STEP(OBSP, WQ, KK) do { \
    float4 a4 = *(const float4*)((OBSP) + (KK)*64); \
    ulonglong2 wA = (WQ)[(KK)*16]; \
    ulonglong2 wB = (WQ)[(KK)*16 + 1]; \
    u64 ab0 = pack2(a4.x), ab1 = pack2(a4.y), ab2 = pack2(a4.z), ab3 = pack2(a4.w); \
    acc[0]  = ffma2(ab0, wA.x, acc[0]);  acc[1]  = ffma2(ab0, wA.y, acc[1]); \
    acc[2]  = ffma2(ab0, wB.x, acc[2]);  acc[3]  = ffma2(ab0, wB.y, acc[3]); \
    acc[4]  = ffma2(ab1, wA.x, acc[4]);  acc[5]  = ffma2(ab1, wA.y, acc[5]); \
    acc[6]  = ffma2(ab1, wB.x, acc[6]);  acc[7]  = ffma2(ab1, wB.y, acc[7]); \
    acc[8]  = ffma2(ab2, wA.x, acc[8]);  acc[9]  = ffma2(ab2, wA.y, acc[9]); \
    acc[10] = ffma2(ab2, wB.x, acc[10]); acc[11] = ffma2(ab2, wB.y, acc[11]); \
    acc[12] = ffma2(ab3, wA.x, acc[12]); acc[13] = ffma2(ab3, wA.y, acc[13]); \
    acc[14] = ffma2(ab3, wB.x, acc[14]); acc[15] = ffma2(ab3, wB.y, acc[15]); \
} while(0)

// epilogue: relu(acc + bias) transposed into SHR [64][64]
#define EPILOGUE(SBX) do { \
    _Pragma("unroll") \
    for (int p = 0; p < 4; p++){ \
        float blo = sm[(SBX) + 8*ty + 2*p]; \
        float bhi = sm[(SBX) + 8*ty + 2*p + 1]; \
        float2 f0 = unpack2(acc[0*4+p]); \
        float2 f1 = unpack2(acc[1*4+p]); \
        float2 f2 = unpack2(acc[2*4+p]); \
        float2 f3 = unpack2(acc[3*4+p]); \
        float4 lo, hi; \
        lo.x = fmaxf(f0.x + blo, 0.0f); lo.y = fmaxf(f1.x + blo, 0.0f); \
        lo.z = fmaxf(f2.x + blo, 0.0f); lo.w = fmaxf(f3.x + blo, 0.0f); \
        hi.x = fmaxf(f0.y + bhi, 0.0f); hi.y = fmaxf(f1.y + bhi, 0.0f); \
        hi.z = fmaxf(f2.y + bhi, 0.0f); hi.w = fmaxf(f3.y + bhi, 0.0f); \
        *(float4*)(sm + SHR + (8*ty + 2*p    )*64 + 4*tx) = lo; \
        *(float4*)(sm + SHR + (8*ty + 2*p + 1)*64 + 4*tx) = hi; \
    } \
} while(0)

__global__ __launch_bounds__(BPB, 4) void maddpg_v4_kernel(
    const float* __restrict__ x,
    const float* __restrict__ W1, const float* __restrict__ b1,
    const float* __restrict__ W2, const float* __restrict__ b2,
    const float* __restrict__ W3, const float* __restrict__ b3,
    const int* __restrict__ idx,
    float* __restrict__ out, int B)
{
    extern __shared__ float sm[];
    __shared__ int sIdx[8];
    __shared__ int sActive[5];
    const int tid = threadIdx.x;
    const int tx  = tid & 15;    // batch quad: batches 4tx..4tx+3
    const int ty  = tid >> 4;    // output octet: outputs 8ty..8ty+7
    const u32 smb = smaddr(sm);
    const int b0  = blockIdx.x * TILEB;
    const long nf2 = (long)B * 70;   // total float2 in x

    // ---- issue stage wave 0 (16 batches) via cp.async, then load weights ----
    {
        long gbase = (long)b0 * 70;
        #pragma unroll
        for (int j = 0; j < 9; j++){
            int i = j*BPB + tid;
            if (i < 1120){
                long gi = gbase + i;
                if (gi < nf2){
                    u32 dst = smb + (u32)((XST + (i/70)*142 + (i%70)*2) * 4);
                    cp8(dst, (const float2*)x + gi);
                }
            }
        }
        CP_COMMIT();
    }
    if (tid < 8)  sIdx[tid] = idx[tid];
    if (tid < 5)  sActive[tid] = 0;
    // W1 compacted to 36 rows (drop structurally-zero obs rows)
    #pragma unroll
    for (int j = 0; j < 5; j++){
        int i = j*BPB + tid;           // over 576 float4
        if (i < 576){
            int ck = i >> 4, nq = i & 15;
            int o;
            if (ck < 5)       o = ck;
            else if (ck < 11) { int m = (ck-5) >> 1; o = 5 + 3*m + ((ck-5)&1); }
            else              o = 14 + (ck - 11);
            ((float4*)(sm + SW1))[i] = ((const float4*)W1)[o*16 + nq];
        }
    }
    #pragma unroll
    for (int j = 0; j < 8; j++)
        ((float4*)(sm + SW2))[j*BPB + tid] = ((const float4*)W2)[j*BPB + tid];
    if (tid < 16) ((float4*)(sm + SB1))[tid] = ((const float4*)b1)[tid];
    else if (tid < 32) ((float4*)(sm + SB2))[tid-16] = ((const float4*)b2)[tid-16];
    if (tid < 64){
        float a1 = W3[tid*5+1], a2 = W3[tid*5+2], a3 = W3[tid*5+3], a4 = W3[tid*5+4];
        ((float2*)(sm + SWD))[tid] = make_float2(a1 - a2, a3 - a4);
    }
    if (tid == 0) *(float2*)(sm + SCC) = make_float2(b3[1]-b3[2], b3[3]-b3[4]);

    // ---- 4 staging waves: wait, build obs for 16 batches (8 threads/batch), next wave ----
    #pragma unroll 1
    for (int w = 0; w < 4; w++){
        CP_WAIT0();
        __syncthreads();
        {
            const int lb = tid >> 3, s = tid & 7;
            const float* xb = sm + XST + lb*142;
            const float p0 = xb[0], p1 = xb[1];
            float* ob = sm + SHR + (w*16 + lb);
            if (s == 0){
                ob[0*64] = p0;   ob[1*64] = p1;   ob[2*64] = xb[2];
                ob[3*64] = xb[3]; ob[4*64] = xb[4];
                const float* r = xb + (sIdx[7] + 10)*7;      // obstacle 4
                float dx = r[0]-p0, dy = r[1]-p1;
                bool in = (dx*dx + dy*dy) < 0.0225f;
                if (in) sActive[4] = 1;
                ob[31*64] = in ? dx   : 0.0f;
                ob[32*64] = in ? dy   : 0.0f;
                ob[33*64] = in ? r[2] : 0.0f;
                ob[34*64] = in ? r[3] : 0.0f;
                ob[35*64] = in ? r[4] : 0.0f;
            } else if (s < 4){
                int m = s - 1;
                const float* r = xb + sIdx[m]*7;
                ob[(5+2*m)*64] = (r[5] + r[0]) - p0;
                ob[(6+2*m)*64] = (r[6] + r[1]) - p1;
            } else {
                int m = s - 4;                                // obstacles 0..3
                const float* r = xb + (sIdx[3+m] + 10)*7;
                float dx = r[0]-p0, dy = r[1]-p1;
                bool in = (dx*dx + dy*dy) < 0.0225f;
                if (in) sActive[m] = 1;
                int kb = 11 + 5*m;
                ob[(kb+0)*64] = in ? dx   : 0.0f;
                ob[(kb+1)*64] = in ? dy   : 0.0f;
                ob[(kb+2)*64] = in ? r[2] : 0.0f;
                ob[(kb+3)*64] = in ? r[3] : 0.0f;
                ob[(kb+4)*64] = in ? r[4] : 0.0f;
            }
        }
        __syncthreads();     // XST consumed, SOBS wave visible
        if (w < 3){
            long gbase = (long)(b0 + (w+1)*16) * 70;
            #pragma unroll
            for (int j = 0; j < 9; j++){
                int i = j*BPB + tid;
                if (i < 1120){
                    long gi = gbase + i;
                    if (gi < nf2){
                        u32 dst = smb + (u32)((XST + (i/70)*142 + (i%70)*2) * 4);
                        cp8(dst, (const float2*)x + gi);
                    }
                }
            }
            CP_COMMIT();
        }
    }

    int act0 = sActive[0], act1 = sActive[1], act2 = sActive[2],
        act3 = sActive[3], act4 = sActive[4];

    // ---- GEMM1: [64 x 36] * [36 x 64], obstacle row-groups skipped when tile-inactive ----
    u64 acc[16];
    #pragma unroll
    for (int i = 0; i < 16; i++) acc[i] = 0ull;
    {
        const float* obsp = sm + SHR + 4*tx;
        const ulonglong2* wq = (const ulonglong2*)(sm + SW1 + 8*ty);
        #pragma unroll
        for (int k = 0; k < 11; k++) K_STEP(obsp, wq, k);
        if (act0){
            #pragma unroll
            for (int k = 11; k < 16; k++) K_STEP(obsp, wq, k);
        }
        if (act1){
            #pragma unroll
            for (int k = 16; k < 21; k++) K_STEP(obsp, wq, k);
        }
        if (act2){
            #pragma unroll
            for (int k = 21; k < 26; k++) K_STEP(obsp, wq, k);
        }
        if (act3){
            #pragma unroll
            for (int k = 26; k < 31; k++) K_STEP(obsp, wq, k);
        }
        if (act4){
            #pragma unroll
            for (int k = 31; k < 36; k++) K_STEP(obsp, wq, k);
        }
    }
    __syncthreads();           // SOBS reads complete before SH1 overwrites region
    EPILOGUE(SB1);
    __syncthreads();

    // ---- GEMM2: [64 x 64] * [64 x 64] ----
    #pragma unroll
    for (int i = 0; i < 16; i++) acc[i] = 0ull;
    {
        const float* hp = sm + SHR + 4*tx;
        const ulonglong2* wq = (const ulonglong2*)(sm + SW2 + 8*ty);
        #pragma unroll 16
        for (int k = 0; k < 64; k++) K_STEP(hp, wq, k);
    }
    __syncthreads();           // SH1 reads complete before g overwrites region
    EPILOGUE(SB2);
    __syncthreads();

    // ---- fold with W3 diffs, scale, clip, store ----
    if (tid < TILEB){
        u64 a2 = *(const u64*)(sm + SCC);
        const u64* wd = (const u64*)(sm + SWD);
        const float* g = sm + SHR + tid;
        #pragma unroll 8
        for (int o = 0; o < 64; o++)
            a2 = ffma2(pack2(g[o*64]), wd[o], a2);
        float2 r = unpack2(a2);
        float v0 = r.x * 0.1f, v1 = r.y * 0.1f;
        if (fabsf(v0) > 1.0f) v0 = copysignf(2.0f, v0);
        if (fabsf(v1) > 1.0f) v1 = copysignf(2.0f, v1);
        int b = b0 + tid;
        if (b < B) ((float2*)out)[b] = make_float2(v0, v1);
    }
}

extern "C" void kernel_launch(void* const* d_in, const int* in_sizes, int n_in,
                              void* d_out, int out_size)
{
    const float* x  = (const float*)d_in[0];
    const float* W1 = (const float*)d_in[1];
    const float* b1 = (const float*)d_in[2];
    const float* W2 = (const float*)d_in[3];
    const float* b2 = (const float*)d_in[4];
    const float* W3 = (const float*)d_in[5];
    const float* b3 = (const float*)d_in[6];
    const int*  idx = (const int*)d_in[7];

    const int B = in_sizes[0] / 140;
    const int blocks = (B + TILEB - 1) / TILEB;
    const size_t smem = SMEM_FLOATS * sizeof(float);

    cudaFuncSetAttribute(maddpg_v4_kernel,
                         cudaFuncAttributeMaxDynamicSharedMemorySize, (int)smem);

    maddpg_v4_kernel<<<blocks, BPB, smem>>>(x, W1, b1, W2, b2, W3, b3, idx,
                                            (float*)d_out, B);
}